// round 1
// baseline (speedup 1.0000x reference)
#include <cuda_runtime.h>
#include <cstdint>

// Problem constants (from reference): F=50000, K=32, E=128, N_NODE=100000
#define KNBR 32
#define EMB  128
#define MAXF 50000

// Scratch for agg[F, E] (no cudaMalloc allowed)
__device__ float g_agg[MAXF * EMB];

// ---------------------------------------------------------------------------
// Kernel A: gather neighbors, rank-1 attention softmax, weighted aggregate.
// One block per feature f. 128 threads (4 warps).
// SMEM: neigh tile 32x128 fp32 (16KB) read once from L2, used twice.
// ---------------------------------------------------------------------------
__global__ __launch_bounds__(128) void attn_agg_kernel(
    const int* __restrict__ adj,      // [F, 32] int32
    const float* __restrict__ emb_i,  // [N, 128]
    const float* __restrict__ u)      // [128]
{
    __shared__ float s_neigh[KNBR * EMB];   // [k][e]
    __shared__ float s_alpha[KNBR];
    __shared__ int   s_adj[KNBR];
    __shared__ float s_u[EMB];

    const int f   = blockIdx.x;
    const int tid = threadIdx.x;

    if (tid < KNBR) s_adj[tid] = adj[f * KNBR + tid];
    s_u[tid] = u[tid];
    __syncthreads();

    // Gather: 32 rows x 32 float4 = 1024 float4 across 128 threads (8 each)
    const float4* emb4 = reinterpret_cast<const float4*>(emb_i);
    float4* sn4 = reinterpret_cast<float4*>(s_neigh);
#pragma unroll
    for (int r = 0; r < 8; r++) {
        int i = tid + r * 128;
        int k = i >> 5;
        int q = i & 31;
        sn4[k * 32 + q] = emb4[(long long)s_adj[k] * 32 + q];
    }
    __syncthreads();

    // alpha_k = dot(neigh_k, u) + mask. Warp w handles k = w*8 .. w*8+7
    const int w = tid >> 5;
    const int l = tid & 31;
#pragma unroll
    for (int kk = 0; kk < 8; kk++) {
        int k = w * 8 + kk;
        const float* row = &s_neigh[k * EMB];
        float s = row[l] * s_u[l]
                + row[l + 32] * s_u[l + 32]
                + row[l + 64] * s_u[l + 64]
                + row[l + 96] * s_u[l + 96];
#pragma unroll
        for (int off = 16; off > 0; off >>= 1)
            s += __shfl_down_sync(0xffffffffu, s, off);
        if (l == 0)
            s_alpha[k] = s + (s_adj[k] != 0 ? 0.0f : -10000.0f);
    }
    __syncthreads();

    // Softmax over 32 entries: warp 0
    if (w == 0) {
        float a = s_alpha[l];
        float m = a;
#pragma unroll
        for (int off = 16; off > 0; off >>= 1)
            m = fmaxf(m, __shfl_xor_sync(0xffffffffu, m, off));
        float e = __expf(a - m);
        float sum = e;
#pragma unroll
        for (int off = 16; off > 0; off >>= 1)
            sum += __shfl_xor_sync(0xffffffffu, sum, off);
        s_alpha[l] = e / sum;
    }
    __syncthreads();

    // agg[e] = sum_k alpha[k] * neigh[k][e]
    float acc = 0.0f;
#pragma unroll
    for (int k = 0; k < KNBR; k++)
        acc = fmaf(s_alpha[k], s_neigh[k * EMB + tid], acc);
    g_agg[f * EMB + tid] = acc;
}

// ---------------------------------------------------------------------------
// Kernel B: gate = sigmoid(cat([emb_f, agg]) @ W.T + b); out = gate*emb_f +
// (1-gate)*agg. Tiled SIMT GEMM: TM=64 f-rows per block, full E=128 out cols,
// K-dim (256) in 4 chunks of 64. 256 threads, 4f x 8e register micro-tile.
// cat tile natural [f][j] (broadcast reads); W tile transposed [j][e] for
// conflict-free vectorized inner-loop reads.
// ---------------------------------------------------------------------------
#define TM 64
#define TK 64
#define CAT_LD 68    // 68*4 = 272 bytes, 16B aligned rows
#define W_LD  132    // 132*4 = 528 bytes, 16B aligned rows

__global__ __launch_bounds__(256) void gate_fuse_kernel(
    const float* __restrict__ emb_f,  // [F, 128]
    const float* __restrict__ W,      // [128, 256] row-major (out_e, in_j)
    const float* __restrict__ bias,   // [128]
    float* __restrict__ out,          // [F, 128]
    int F)
{
    __shared__ float s_cat[TM * CAT_LD];   // [f][j]
    __shared__ float s_W[TK * W_LD];       // [j][e]

    const int t  = threadIdx.x;
    const int tx = t & 15;       // e-group: e = tx*8 .. tx*8+7
    const int ty = t >> 4;       // f-group: f = ty*4 .. ty*4+3
    const int fbase = blockIdx.x * TM;

    float acc[4][8];
#pragma unroll
    for (int i = 0; i < 4; i++)
#pragma unroll
        for (int j = 0; j < 8; j++) acc[i][j] = 0.0f;

    for (int kk = 0; kk < 4; kk++) {
        // cat chunk source: kk 0,1 -> emb_f cols [0,128); kk 2,3 -> agg
        const float* src = (kk < 2) ? (emb_f + kk * 64) : (g_agg + (kk - 2) * 64);

        // Load cat chunk: 64f x 64j = 1024 float4, 4 per thread.
#pragma unroll
        for (int r = 0; r < 4; r++) {
            int id = t + 256 * r;
            int fl = id >> 4;           // 0..63
            int jq = id & 15;           // float4 index along j
            int gf = fbase + fl; if (gf >= F) gf = F - 1;
            float4 v = *reinterpret_cast<const float4*>(src + (long long)gf * EMB + jq * 4);
            *reinterpret_cast<float4*>(&s_cat[fl * CAT_LD + jq * 4]) = v;
        }
        // Load W chunk transposed: 128e x 64j = 2048 float4, 8 per thread.
#pragma unroll
        for (int r = 0; r < 8; r++) {
            int id = t + 256 * r;
            int e  = id >> 4;           // 0..127
            int jq = id & 15;
            float4 v = *reinterpret_cast<const float4*>(W + e * 256 + kk * 64 + jq * 4);
            s_W[(jq * 4 + 0) * W_LD + e] = v.x;
            s_W[(jq * 4 + 1) * W_LD + e] = v.y;
            s_W[(jq * 4 + 2) * W_LD + e] = v.z;
            s_W[(jq * 4 + 3) * W_LD + e] = v.w;
        }
        __syncthreads();

#pragma unroll 16
        for (int j = 0; j < TK; j++) {
            float c0 = s_cat[(ty * 4 + 0) * CAT_LD + j];
            float c1 = s_cat[(ty * 4 + 1) * CAT_LD + j];
            float c2 = s_cat[(ty * 4 + 2) * CAT_LD + j];
            float c3 = s_cat[(ty * 4 + 3) * CAT_LD + j];
            float4 w0 = *reinterpret_cast<const float4*>(&s_W[j * W_LD + tx * 8]);
            float4 w1 = *reinterpret_cast<const float4*>(&s_W[j * W_LD + tx * 8 + 4]);
            float wv[8] = {w0.x, w0.y, w0.z, w0.w, w1.x, w1.y, w1.z, w1.w};
#pragma unroll
            for (int ee = 0; ee < 8; ee++) {
                acc[0][ee] = fmaf(c0, wv[ee], acc[0][ee]);
                acc[1][ee] = fmaf(c1, wv[ee], acc[1][ee]);
                acc[2][ee] = fmaf(c2, wv[ee], acc[2][ee]);
                acc[3][ee] = fmaf(c3, wv[ee], acc[3][ee]);
            }
        }
        __syncthreads();
    }

    // Epilogue: gate + blend
    const float4* b4 = reinterpret_cast<const float4*>(bias);
    float4 bv0 = b4[tx * 2];
    float4 bv1 = b4[tx * 2 + 1];
    float bb[8] = {bv0.x, bv0.y, bv0.z, bv0.w, bv1.x, bv1.y, bv1.z, bv1.w};

#pragma unroll
    for (int ff = 0; ff < 4; ff++) {
        int f = fbase + ty * 4 + ff;
        if (f >= F) continue;
        const float* efp = emb_f + (long long)f * EMB + tx * 8;
        const float* agp = g_agg + (long long)f * EMB + tx * 8;
        float4 e0 = *reinterpret_cast<const float4*>(efp);
        float4 e1 = *reinterpret_cast<const float4*>(efp + 4);
        float4 a0 = *reinterpret_cast<const float4*>(agp);
        float4 a1 = *reinterpret_cast<const float4*>(agp + 4);
        float ef[8] = {e0.x, e0.y, e0.z, e0.w, e1.x, e1.y, e1.z, e1.w};
        float ag[8] = {a0.x, a0.y, a0.z, a0.w, a1.x, a1.y, a1.z, a1.w};
        float o[8];
#pragma unroll
        for (int ee = 0; ee < 8; ee++) {
            float x = acc[ff][ee] + bb[ee];
            float g = 1.0f / (1.0f + __expf(-x));
            o[ee] = g * ef[ee] + (1.0f - g) * ag[ee];
        }
        float4 o0 = make_float4(o[0], o[1], o[2], o[3]);
        float4 o1 = make_float4(o[4], o[5], o[6], o[7]);
        float* op = out + (long long)f * EMB + tx * 8;
        *reinterpret_cast<float4*>(op)     = o0;
        *reinterpret_cast<float4*>(op + 4) = o1;
    }
}

// ---------------------------------------------------------------------------
extern "C" void kernel_launch(void* const* d_in, const int* in_sizes, int n_in,
                              void* d_out, int out_size)
{
    const int*   adj   = (const int*)d_in[0];     // [F,32] int32
    const float* emb_i = (const float*)d_in[1];   // [N,128]
    const float* emb_f = (const float*)d_in[2];   // [F,128]
    const float* u     = (const float*)d_in[3];   // [128]
    const float* W     = (const float*)d_in[4];   // [128,256]
    const float* bias  = (const float*)d_in[5];   // [128]
    float*       out   = (float*)d_out;           // [F,128]

    const int F = in_sizes[0] / KNBR;

    attn_agg_kernel<<<F, 128>>>(adj, emb_i, u);
    gate_fuse_kernel<<<(F + TM - 1) / TM, 256>>>(emb_f, W, bias, out, F);
}

// round 2
// speedup vs baseline: 1.5073x; 1.5073x over previous
#include <cuda_runtime.h>
#include <cstdint>

// Problem constants: F=50000, K=32, E=128, N_NODE=100000
#define KNBR 32
#define EMB  128
#define MAXF 50000
#define MAXN 100000

// Scratch (no cudaMalloc allowed)
__device__ float g_agg[MAXF * EMB];     // 25.6 MB
__device__ float g_alpha[MAXF * KNBR];  // 6.4 MB
__device__ float g_p[MAXN];             // 0.4 MB

__device__ __forceinline__ unsigned long long fma_f32x2(
    unsigned long long a, unsigned long long b, unsigned long long c)
{
    unsigned long long d;
    asm("fma.rn.f32x2 %0, %1, %2, %3;" : "=l"(d) : "l"(a), "l"(b), "l"(c));
    return d;
}

// ---------------------------------------------------------------------------
// Kernel P: p[n] = dot(emb_i[n], u). Warp per node.
// ---------------------------------------------------------------------------
__global__ __launch_bounds__(256) void p_kernel(
    const float* __restrict__ emb_i, const float* __restrict__ u, int N)
{
    int gw   = (blockIdx.x * 256 + threadIdx.x) >> 5;
    int lane = threadIdx.x & 31;
    if (gw >= N) return;
    float4 v  = *reinterpret_cast<const float4*>(emb_i + (size_t)gw * EMB + lane * 4);
    float4 uu = *reinterpret_cast<const float4*>(u + lane * 4);
    float s = v.x * uu.x + v.y * uu.y + v.z * uu.z + v.w * uu.w;
#pragma unroll
    for (int off = 16; off > 0; off >>= 1)
        s += __shfl_xor_sync(0xffffffffu, s, off);
    if (lane == 0) g_p[gw] = s;
}

// ---------------------------------------------------------------------------
// Kernel A0: alpha[f,k] = softmax_k(p[adj[f,k]] + mask). Warp per feature.
// ---------------------------------------------------------------------------
__global__ __launch_bounds__(256) void alpha_kernel(
    const int* __restrict__ adj, int F)
{
    int f    = blockIdx.x * 8 + (threadIdx.x >> 5);
    int lane = threadIdx.x & 31;
    if (f >= F) return;
    int idx = adj[f * KNBR + lane];
    float a = g_p[idx] + (idx != 0 ? 0.0f : -10000.0f);
    float m = a;
#pragma unroll
    for (int off = 16; off > 0; off >>= 1)
        m = fmaxf(m, __shfl_xor_sync(0xffffffffu, m, off));
    float e = __expf(a - m);
    float sum = e;
#pragma unroll
    for (int off = 16; off > 0; off >>= 1)
        sum += __shfl_xor_sync(0xffffffffu, sum, off);
    g_alpha[f * KNBR + lane] = e / sum;
}

// ---------------------------------------------------------------------------
// Kernel B: agg[f,e] = sum_k alpha[f,k] * emb_i[adj[f,k], e].
// 256 threads = 2 features; thread owns one e. alpha/idx register-resident,
// 32 independent coalesced L2 loads per thread.
// ---------------------------------------------------------------------------
__global__ __launch_bounds__(256) void agg_kernel(
    const int* __restrict__ adj, const float* __restrict__ emb_i, int F)
{
    __shared__ int   s_idx[2][KNBR];
    __shared__ float s_al [2][KNBR];

    const int t    = threadIdx.x;
    const int half = t >> 7;
    const int e    = t & 127;
    const int f    = blockIdx.x * 2 + half;

    if (t < 64) {
        int h = t >> 5, lane = t & 31;
        int ff = blockIdx.x * 2 + h;
        if (ff < F) {
            s_idx[h][lane] = adj[(size_t)ff * KNBR + lane];
            s_al [h][lane] = g_alpha[(size_t)ff * KNBR + lane];
        }
    }
    __syncthreads();
    if (f >= F) return;

    int   idx[KNBR];
    float al [KNBR];
    const int4*   si4 = reinterpret_cast<const int4*>(s_idx[half]);
    const float4* sa4 = reinterpret_cast<const float4*>(s_al[half]);
#pragma unroll
    for (int q = 0; q < 8; q++) {
        int4   iv = si4[q];
        float4 av = sa4[q];
        idx[q*4+0] = iv.x; idx[q*4+1] = iv.y; idx[q*4+2] = iv.z; idx[q*4+3] = iv.w;
        al [q*4+0] = av.x; al [q*4+1] = av.y; al [q*4+2] = av.z; al [q*4+3] = av.w;
    }

    float acc = 0.0f;
#pragma unroll
    for (int k = 0; k < KNBR; k++)
        acc = fmaf(al[k], __ldg(emb_i + (size_t)((unsigned)idx[k]) * EMB + e), acc);

    g_agg[(size_t)f * EMB + e] = acc;
}

// ---------------------------------------------------------------------------
// Kernel C: gate = sigmoid(cat([emb_f, agg]) @ W.T + b);
//           out = gate*emb_f + (1-gate)*agg.
// 64-f tile, 256 threads, 4f x 8e micro-tile. FFMA2 (f32x2) paired along the
// K(j) dimension: c pairs contiguous in s_cat (b64 loads, zero packing);
// w pairs contiguous via (j-pair, e)-interleaved s_Wp layout.
// Thread tx owns e in {2tx+32m, 2tx+1+32m : m=0..3} (conflict-free).
// ---------------------------------------------------------------------------
#define TM 64
#define TK 64
#define CAT_LD 68     // floats; 272B rows, 16B aligned
#define W2_LD  260    // floats; 1040B rows, 16B aligned

__global__ __launch_bounds__(256) void gate_fuse_kernel(
    const float* __restrict__ emb_f,  // [F, 128]
    const float* __restrict__ W,      // [128, 256]
    const float* __restrict__ bias,   // [128]
    float* __restrict__ out,          // [F, 128]
    int F)
{
    __shared__ float s_cat[TM * CAT_LD];   // [f][j]
    __shared__ float s_Wp [32 * W2_LD];    // [j2][e] float2 pairs (j, j+1)

    const int t  = threadIdx.x;
    const int tx = t & 15;
    const int ty = t >> 4;
    const int fbase = blockIdx.x * TM;

    unsigned long long acc2[4][8];
#pragma unroll
    for (int i = 0; i < 4; i++)
#pragma unroll
        for (int j = 0; j < 8; j++) acc2[i][j] = 0ULL;

#pragma unroll 1
    for (int kk = 0; kk < 4; kk++) {
        const float* src = (kk < 2) ? (emb_f + kk * 64) : (g_agg + (kk - 2) * 64);

        // cat chunk: 64f x 64j, natural layout
#pragma unroll
        for (int r = 0; r < 4; r++) {
            int id = t + 256 * r;
            int fl = id >> 4;
            int jq = id & 15;
            int gf = fbase + fl; if (gf >= F) gf = F - 1;
            float4 v = *reinterpret_cast<const float4*>(src + (size_t)gf * EMB + jq * 4);
            *reinterpret_cast<float4*>(&s_cat[fl * CAT_LD + jq * 4]) = v;
        }
        // W chunk: transpose into (j-pair, e) interleaved layout
#pragma unroll
        for (int r = 0; r < 8; r++) {
            int id = t + 256 * r;
            int e  = id >> 4;           // 0..127
            int jq = id & 15;           // j = jq*4 .. jq*4+3
            float4 v = *reinterpret_cast<const float4*>(W + e * 256 + kk * 64 + jq * 4);
            *reinterpret_cast<float2*>(&s_Wp[(2*jq)     * W2_LD + 2*e]) = make_float2(v.x, v.y);
            *reinterpret_cast<float2*>(&s_Wp[(2*jq + 1) * W2_LD + 2*e]) = make_float2(v.z, v.w);
        }
        __syncthreads();

#pragma unroll
        for (int q = 0; q < 16; q++) {     // q covers j = 4q..4q+3 (2 j2-steps)
            ulonglong2 cq[4];
#pragma unroll
            for (int fr = 0; fr < 4; fr++)
                cq[fr] = *reinterpret_cast<const ulonglong2*>(
                    &s_cat[(ty * 4 + fr) * CAT_LD + q * 4]);
#pragma unroll
            for (int h = 0; h < 2; h++) {
                int j2 = 2 * q + h;
#pragma unroll
                for (int m = 0; m < 4; m++) {
                    ulonglong2 wq = *reinterpret_cast<const ulonglong2*>(
                        &s_Wp[j2 * W2_LD + (2 * tx + 32 * m) * 2]);
#pragma unroll
                    for (int fr = 0; fr < 4; fr++) {
                        unsigned long long c = h ? cq[fr].y : cq[fr].x;
                        acc2[fr][2*m]     = fma_f32x2(c, wq.x, acc2[fr][2*m]);
                        acc2[fr][2*m + 1] = fma_f32x2(c, wq.y, acc2[fr][2*m + 1]);
                    }
                }
            }
        }
        __syncthreads();
    }

    // Epilogue: gate + blend. Thread e's: {2tx+32m, 2tx+1+32m}
    float bb[8];
#pragma unroll
    for (int m = 0; m < 4; m++) {
        float2 b = *reinterpret_cast<const float2*>(&bias[2 * tx + 32 * m]);
        bb[2*m] = b.x; bb[2*m + 1] = b.y;
    }

#pragma unroll
    for (int fr = 0; fr < 4; fr++) {
        int f = fbase + ty * 4 + fr;
        if (f >= F) continue;
        const float* efp = emb_f + (size_t)f * EMB;
        const float* agp = g_agg + (size_t)f * EMB;
        float*       op  = out   + (size_t)f * EMB;
#pragma unroll
        for (int m = 0; m < 4; m++) {
            int e0 = 2 * tx + 32 * m;
            float2 pa = *reinterpret_cast<float2*>(&acc2[fr][2*m]);
            float2 pb = *reinterpret_cast<float2*>(&acc2[fr][2*m + 1]);
            float x0 = pa.x + pa.y + bb[2*m];
            float x1 = pb.x + pb.y + bb[2*m + 1];
            float g0 = 1.0f / (1.0f + __expf(-x0));
            float g1 = 1.0f / (1.0f + __expf(-x1));
            float2 ef = *reinterpret_cast<const float2*>(efp + e0);
            float2 ag = *reinterpret_cast<const float2*>(agp + e0);
            float2 o;
            o.x = g0 * ef.x + (1.0f - g0) * ag.x;
            o.y = g1 * ef.y + (1.0f - g1) * ag.y;
            *reinterpret_cast<float2*>(op + e0) = o;
        }
    }
}

// ---------------------------------------------------------------------------
extern "C" void kernel_launch(void* const* d_in, const int* in_sizes, int n_in,
                              void* d_out, int out_size)
{
    const int*   adj   = (const int*)d_in[0];     // [F,32]
    const float* emb_i = (const float*)d_in[1];   // [N,128]
    const float* emb_f = (const float*)d_in[2];   // [F,128]
    const float* u     = (const float*)d_in[3];   // [128]
    const float* W     = (const float*)d_in[4];   // [128,256]
    const float* bias  = (const float*)d_in[5];   // [128]
    float*       out   = (float*)d_out;           // [F,128]

    const int F = in_sizes[0] / KNBR;
    const int N = in_sizes[1] / EMB;

    p_kernel<<<(N * 32 + 255) / 256, 256>>>(emb_i, u, N);
    alpha_kernel<<<(F + 7) / 8, 256>>>(adj, F);
    agg_kernel<<<(F + 1) / 2, 256>>>(adj, emb_i, F);
    gate_fuse_kernel<<<(F + TM - 1) / TM, 256>>>(emb_f, W, bias, out, F);
}

// round 3
// speedup vs baseline: 1.8712x; 1.2414x over previous
#include <cuda_runtime.h>
#include <cuda_fp16.h>
#include <cstdint>

// Problem constants: F=50000, K=32, E=128, N_NODE=100000
#define KNBR 32
#define EMB  128
#define MAXF 50000
#define MAXN 100000

// Scratch (no cudaMalloc allowed)
__device__ float g_agg[MAXF * EMB];                      // 25.6 MB
__device__ float g_alpha[MAXF * KNBR];                   // 6.4 MB
__device__ float g_p[MAXN];                              // 0.4 MB
__device__ alignas(16) __half g_emb_h[MAXN * EMB];       // 25.6 MB

__device__ __forceinline__ unsigned long long fma_f32x2(
    unsigned long long a, unsigned long long b, unsigned long long c)
{
    unsigned long long d;
    asm("fma.rn.f32x2 %0, %1, %2, %3;" : "=l"(d) : "l"(a), "l"(b), "l"(c));
    return d;
}

__device__ __forceinline__ void cp_async16(uint32_t saddr, const void* gaddr)
{
    asm volatile("cp.async.cg.shared.global [%0], [%1], 16;"
                 :: "r"(saddr), "l"(gaddr));
}

// ---------------------------------------------------------------------------
// Kernel P: p[n] = dot(emb_i[n], u); also writes fp16 copy of emb_i.
// Warp per node.
// ---------------------------------------------------------------------------
__global__ __launch_bounds__(256) void p_kernel(
    const float* __restrict__ emb_i, const float* __restrict__ u, int N)
{
    int gw   = (blockIdx.x * 256 + threadIdx.x) >> 5;
    int lane = threadIdx.x & 31;
    if (gw >= N) return;
    float4 v  = *reinterpret_cast<const float4*>(emb_i + (size_t)gw * EMB + lane * 4);
    float4 uu = *reinterpret_cast<const float4*>(u + lane * 4);

    // fp16 copy (8B per lane, coalesced 256B per warp)
    __half2 h0 = __float22half2_rn(make_float2(v.x, v.y));
    __half2 h1 = __float22half2_rn(make_float2(v.z, v.w));
    uint2 hw;
    hw.x = *reinterpret_cast<uint32_t*>(&h0);
    hw.y = *reinterpret_cast<uint32_t*>(&h1);
    *reinterpret_cast<uint2*>(&g_emb_h[(size_t)gw * EMB + lane * 4]) = hw;

    float s = v.x * uu.x + v.y * uu.y + v.z * uu.z + v.w * uu.w;
#pragma unroll
    for (int off = 16; off > 0; off >>= 1)
        s += __shfl_xor_sync(0xffffffffu, s, off);
    if (lane == 0) g_p[gw] = s;
}

// ---------------------------------------------------------------------------
// Kernel A0: alpha[f,k] = softmax_k(p[adj[f,k]] + mask). Warp per feature.
// ---------------------------------------------------------------------------
__global__ __launch_bounds__(256) void alpha_kernel(
    const int* __restrict__ adj, int F)
{
    int f    = blockIdx.x * 8 + (threadIdx.x >> 5);
    int lane = threadIdx.x & 31;
    if (f >= F) return;
    int idx = adj[f * KNBR + lane];
    float a = g_p[idx] + (idx != 0 ? 0.0f : -10000.0f);
    float m = a;
#pragma unroll
    for (int off = 16; off > 0; off >>= 1)
        m = fmaxf(m, __shfl_xor_sync(0xffffffffu, m, off));
    float e = __expf(a - m);
    float sum = e;
#pragma unroll
    for (int off = 16; off > 0; off >>= 1)
        sum += __shfl_xor_sync(0xffffffffu, sum, off);
    g_alpha[f * KNBR + lane] = e / sum;
}

// ---------------------------------------------------------------------------
// Kernel B: agg[f,e] = sum_k alpha[f,k] * emb_h[adj[f,k], e]  (fp16 gather).
// 256 threads = 4 features; thread owns an e-pair (half2 load, 4B/lane).
// ---------------------------------------------------------------------------
__global__ __launch_bounds__(256) void agg_kernel(
    const int* __restrict__ adj, int F)
{
    __shared__ int   s_idx[4][KNBR];
    __shared__ float s_al [4][KNBR];

    const int t    = threadIdx.x;
    const int sub  = t >> 6;          // feature slot 0..3
    const int ep   = t & 63;          // e-pair index (e = 2*ep)
    const int f    = blockIdx.x * 4 + sub;

    if (t < 128) {
        int h = t >> 5, lane = t & 31;
        int ff = blockIdx.x * 4 + h;
        if (ff < F) {
            s_idx[h][lane] = adj[(size_t)ff * KNBR + lane];
            s_al [h][lane] = g_alpha[(size_t)ff * KNBR + lane];
        }
    }
    __syncthreads();
    if (f >= F) return;

    int   idx[KNBR];
    float al [KNBR];
    const int4*   si4 = reinterpret_cast<const int4*>(s_idx[sub]);
    const float4* sa4 = reinterpret_cast<const float4*>(s_al[sub]);
#pragma unroll
    for (int q = 0; q < 8; q++) {
        int4   iv = si4[q];
        float4 av = sa4[q];
        idx[q*4+0] = iv.x; idx[q*4+1] = iv.y; idx[q*4+2] = iv.z; idx[q*4+3] = iv.w;
        al [q*4+0] = av.x; al [q*4+1] = av.y; al [q*4+2] = av.z; al [q*4+3] = av.w;
    }

    const __half2* eh = reinterpret_cast<const __half2*>(g_emb_h);
    float2 acc = make_float2(0.0f, 0.0f);
#pragma unroll
    for (int k = 0; k < KNBR; k++) {
        __half2 hv = __ldg(eh + (size_t)((unsigned)idx[k]) * (EMB / 2) + ep);
        float2  v  = __half22float2(hv);
        acc.x = fmaf(al[k], v.x, acc.x);
        acc.y = fmaf(al[k], v.y, acc.y);
    }
    *reinterpret_cast<float2*>(&g_agg[(size_t)f * EMB + 2 * ep]) = acc;
}

// ---------------------------------------------------------------------------
// Kernel C (persistent): gate = sigmoid(cat([emb_f, agg]) @ W.T + b);
//           out = gate*emb_f + (1-gate)*agg.
// W resident in smem (FFMA2 (j-pair, e) interleaved layout, loaded once).
// f-tiles of 64 strided over CTAs; cat chunks double-buffered via cp.async.
// 256 threads, 4f x 8e micro-tile, fma.rn.f32x2 inner loop.
// ---------------------------------------------------------------------------
#define TM 64
#define CAT_LD 68     // floats; 272B rows, 16B aligned
#define W2_LD  260    // floats; 1040B rows, 16B aligned
#define SMEM_W_FLOATS   (128 * W2_LD)           // 128 j-pair rows
#define SMEM_CAT_FLOATS (2 * TM * CAT_LD)       // double buffer
#define SMEM_TOTAL_B    ((SMEM_W_FLOATS + SMEM_CAT_FLOATS) * 4)

__global__ __launch_bounds__(256, 1) void gate_fuse_kernel(
    const float* __restrict__ emb_f,  // [F, 128]
    const float* __restrict__ W,      // [128, 256]
    const float* __restrict__ bias,   // [128]
    float* __restrict__ out,          // [F, 128]
    int F)
{
    extern __shared__ float dynsmem[];
    float* s_Wp  = dynsmem;                     // [j2=0..127][2e interleaved]
    float* s_cat = dynsmem + SMEM_W_FLOATS;     // 2 x [64f][64j]

    const int t  = threadIdx.x;
    const int tx = t & 15;
    const int ty = t >> 4;
    const int ntiles = (F + TM - 1) / TM;

    // ---- Load W into smem once, transposed to (j-pair, e) layout ----
#pragma unroll 1
    for (int kk = 0; kk < 4; kk++) {
#pragma unroll
        for (int r = 0; r < 8; r++) {
            int id = t + 256 * r;
            int e  = id >> 4;           // 0..127
            int jq = id & 15;           // j = jq*4..jq*4+3 within chunk
            float4 v = *reinterpret_cast<const float4*>(W + e * 256 + kk * 64 + jq * 4);
            int j2 = kk * 32 + 2 * jq;
            *reinterpret_cast<float2*>(&s_Wp[j2       * W2_LD + 2 * e]) = make_float2(v.x, v.y);
            *reinterpret_cast<float2*>(&s_Wp[(j2 + 1) * W2_LD + 2 * e]) = make_float2(v.z, v.w);
        }
    }
    __syncthreads();

    uint32_t s_cat_u32 = (uint32_t)__cvta_generic_to_shared(s_cat);

    // prefetch helper lambda (chunk kk of tile -> buffer buf)
    auto prefetch = [&](int tile, int kk, int buf) {
        const float* src = (kk < 2) ? (emb_f + kk * 64) : (g_agg + (kk - 2) * 64);
        int fbase = tile * TM;
#pragma unroll
        for (int r = 0; r < 4; r++) {
            int id = t + 256 * r;
            int fl = id >> 4;
            int jq = id & 15;
            int gf = fbase + fl; if (gf >= F) gf = F - 1;
            uint32_t sa = s_cat_u32 + (uint32_t)(((buf * TM + fl) * CAT_LD + jq * 4) * 4);
            cp_async16(sa, src + (size_t)gf * EMB + jq * 4);
        }
    };

    const int tile0 = blockIdx.x;
    if (tile0 < ntiles) {
        prefetch(tile0, 0, 0);
    }
    asm volatile("cp.async.commit_group;");

#pragma unroll 1
    for (int tile = tile0; tile < ntiles; tile += gridDim.x) {
        unsigned long long acc2[4][8];
#pragma unroll
        for (int i = 0; i < 4; i++)
#pragma unroll
            for (int j = 0; j < 8; j++) acc2[i][j] = 0ULL;

#pragma unroll 1
        for (int kk = 0; kk < 4; kk++) {
            // issue prefetch of next chunk into the other buffer
            int nkk = kk + 1, ntile = tile;
            if (nkk == 4) { nkk = 0; ntile = tile + gridDim.x; }
            if (ntile < ntiles) prefetch(ntile, nkk, (kk + 1) & 1);
            asm volatile("cp.async.commit_group;");
            asm volatile("cp.async.wait_group 1;" ::: "memory");
            __syncthreads();

            const float* cbase = s_cat + (kk & 1) * TM * CAT_LD;
            const int j2base = kk * 32;
#pragma unroll
            for (int q = 0; q < 16; q++) {
                ulonglong2 cq[4];
#pragma unroll
                for (int fr = 0; fr < 4; fr++)
                    cq[fr] = *reinterpret_cast<const ulonglong2*>(
                        &cbase[(ty * 4 + fr) * CAT_LD + q * 4]);
#pragma unroll
                for (int h = 0; h < 2; h++) {
                    const float* wrow = &s_Wp[(j2base + 2 * q + h) * W2_LD];
#pragma unroll
                    for (int m = 0; m < 4; m++) {
                        ulonglong2 wq = *reinterpret_cast<const ulonglong2*>(
                            &wrow[(2 * tx + 32 * m) * 2]);
#pragma unroll
                        for (int fr = 0; fr < 4; fr++) {
                            unsigned long long c = h ? cq[fr].y : cq[fr].x;
                            acc2[fr][2*m]     = fma_f32x2(c, wq.x, acc2[fr][2*m]);
                            acc2[fr][2*m + 1] = fma_f32x2(c, wq.y, acc2[fr][2*m + 1]);
                        }
                    }
                }
            }
            __syncthreads();   // buffer (kk&1) free for reuse
        }

        // ---- Epilogue: gate + blend. Thread e's: {2tx+32m, 2tx+1+32m} ----
        int fbase = tile * TM;
        float bb[8];
#pragma unroll
        for (int m = 0; m < 4; m++) {
            float2 b = *reinterpret_cast<const float2*>(&bias[2 * tx + 32 * m]);
            bb[2*m] = b.x; bb[2*m + 1] = b.y;
        }
#pragma unroll
        for (int fr = 0; fr < 4; fr++) {
            int f = fbase + ty * 4 + fr;
            if (f >= F) continue;
            const float* efp = emb_f + (size_t)f * EMB;
            const float* agp = g_agg + (size_t)f * EMB;
            float*       op  = out   + (size_t)f * EMB;
#pragma unroll
            for (int m = 0; m < 4; m++) {
                int e0 = 2 * tx + 32 * m;
                float2 pa = *reinterpret_cast<float2*>(&acc2[fr][2*m]);
                float2 pb = *reinterpret_cast<float2*>(&acc2[fr][2*m + 1]);
                float x0 = pa.x + pa.y + bb[2*m];
                float x1 = pb.x + pb.y + bb[2*m + 1];
                float g0 = 1.0f / (1.0f + __expf(-x0));
                float g1 = 1.0f / (1.0f + __expf(-x1));
                float2 ef = *reinterpret_cast<const float2*>(efp + e0);
                float2 ag = *reinterpret_cast<const float2*>(agp + e0);
                float2 o;
                o.x = g0 * ef.x + (1.0f - g0) * ag.x;
                o.y = g1 * ef.y + (1.0f - g1) * ag.y;
                *reinterpret_cast<float2*>(op + e0) = o;
            }
        }
    }
}

// ---------------------------------------------------------------------------
extern "C" void kernel_launch(void* const* d_in, const int* in_sizes, int n_in,
                              void* d_out, int out_size)
{
    const int*   adj   = (const int*)d_in[0];     // [F,32]
    const float* emb_i = (const float*)d_in[1];   // [N,128]
    const float* emb_f = (const float*)d_in[2];   // [F,128]
    const float* u     = (const float*)d_in[3];   // [128]
    const float* W     = (const float*)d_in[4];   // [128,256]
    const float* bias  = (const float*)d_in[5];   // [128]
    float*       out   = (float*)d_out;           // [F,128]

    const int F = in_sizes[0] / KNBR;
    const int N = in_sizes[1] / EMB;

    int nsm = 148;
    cudaDeviceGetAttribute(&nsm, cudaDevAttrMultiProcessorCount, 0);

    cudaFuncSetAttribute(gate_fuse_kernel,
                         cudaFuncAttributeMaxDynamicSharedMemorySize, SMEM_TOTAL_B);

    p_kernel<<<(N * 32 + 255) / 256, 256>>>(emb_i, u, N);
    alpha_kernel<<<(F + 7) / 8, 256>>>(adj, F);
    agg_kernel<<<(F + 3) / 4, 256>>>(adj, F);

    int ntiles = (F + TM - 1) / TM;
    int nblk = ntiles < nsm ? ntiles : nsm;
    gate_fuse_kernel<<<nblk, 256, SMEM_TOTAL_B>>>(emb_f, W, bias, out, F);
}

// round 4
// speedup vs baseline: 2.9171x; 1.5590x over previous
#include <cuda_runtime.h>
#include <cuda_fp16.h>
#include <cstdint>

// Problem constants: F=50000, K=32, E=128, N_NODE=100000
#define KNBR 32
#define EMB  128
#define MAXF 50000
#define MAXN 100000

// Scratch (no cudaMalloc allowed)
__device__ float g_agg[MAXF * EMB];                      // 25.6 MB
__device__ float g_p[MAXN];                              // 0.4 MB
__device__ alignas(16) __half g_emb_h[MAXN * EMB];       // 25.6 MB

// ---------------------------------------------------------------------------
// PTX helpers
// ---------------------------------------------------------------------------
__device__ __forceinline__ void ldsm_x4(uint32_t& r0, uint32_t& r1,
                                        uint32_t& r2, uint32_t& r3, uint32_t a)
{
    asm volatile("ldmatrix.sync.aligned.m8n8.x4.shared.b16 {%0,%1,%2,%3}, [%4];"
                 : "=r"(r0), "=r"(r1), "=r"(r2), "=r"(r3) : "r"(a));
}
__device__ __forceinline__ void ldsm_x4_t(uint32_t& r0, uint32_t& r1,
                                          uint32_t& r2, uint32_t& r3, uint32_t a)
{
    asm volatile("ldmatrix.sync.aligned.m8n8.x4.trans.shared.b16 {%0,%1,%2,%3}, [%4];"
                 : "=r"(r0), "=r"(r1), "=r"(r2), "=r"(r3) : "r"(a));
}
__device__ __forceinline__ void mma16816(float* d, const uint32_t* a,
                                         uint32_t b0, uint32_t b1)
{
    asm volatile(
        "mma.sync.aligned.m16n8k16.row.col.f32.f16.f16.f32 "
        "{%0,%1,%2,%3}, {%4,%5,%6,%7}, {%8,%9}, {%0,%1,%2,%3};"
        : "+f"(d[0]), "+f"(d[1]), "+f"(d[2]), "+f"(d[3])
        : "r"(a[0]), "r"(a[1]), "r"(a[2]), "r"(a[3]), "r"(b0), "r"(b1));
}

// ---------------------------------------------------------------------------
// Kernel P: p[n] = dot(emb_i[n], u); also writes fp16 copy of emb_i.
// ---------------------------------------------------------------------------
__global__ __launch_bounds__(256) void p_kernel(
    const float* __restrict__ emb_i, const float* __restrict__ u, int N)
{
    int gw   = (blockIdx.x * 256 + threadIdx.x) >> 5;
    int lane = threadIdx.x & 31;
    if (gw >= N) return;
    float4 v  = *reinterpret_cast<const float4*>(emb_i + (size_t)gw * EMB + lane * 4);
    float4 uu = *reinterpret_cast<const float4*>(u + lane * 4);

    __half2 h0 = __float22half2_rn(make_float2(v.x, v.y));
    __half2 h1 = __float22half2_rn(make_float2(v.z, v.w));
    uint2 hw;
    hw.x = *reinterpret_cast<uint32_t*>(&h0);
    hw.y = *reinterpret_cast<uint32_t*>(&h1);
    *reinterpret_cast<uint2*>(&g_emb_h[(size_t)gw * EMB + lane * 4]) = hw;

    float s = v.x * uu.x + v.y * uu.y + v.z * uu.z + v.w * uu.w;
#pragma unroll
    for (int off = 16; off > 0; off >>= 1)
        s += __shfl_xor_sync(0xffffffffu, s, off);
    if (lane == 0) g_p[gw] = s;
}

// ---------------------------------------------------------------------------
// Kernel B: fused alpha-softmax + aggregate.
// agg[f,e] = sum_k softmax_k(p[adj[f,k]]+mask) * emb_h[adj[f,k], e]
// 256 threads = 4 features; first 4 warps do softmax; thread owns an e-pair.
// ---------------------------------------------------------------------------
__global__ __launch_bounds__(256) void agg_kernel(
    const int* __restrict__ adj, int F)
{
    __shared__ int   s_idx[4][KNBR];
    __shared__ float s_al [4][KNBR];

    const int t   = threadIdx.x;
    const int sub = t >> 6;
    const int ep  = t & 63;
    const int f   = blockIdx.x * 4 + sub;

    if (t < 128) {
        int h = t >> 5, lane = t & 31;
        int ff = blockIdx.x * 4 + h;
        if (ff < F) {
            int idx = adj[(size_t)ff * KNBR + lane];
            float a = g_p[idx] + (idx != 0 ? 0.0f : -10000.0f);
            float m = a;
#pragma unroll
            for (int off = 16; off > 0; off >>= 1)
                m = fmaxf(m, __shfl_xor_sync(0xffffffffu, m, off));
            float e = __expf(a - m);
            float sum = e;
#pragma unroll
            for (int off = 16; off > 0; off >>= 1)
                sum += __shfl_xor_sync(0xffffffffu, sum, off);
            s_idx[h][lane] = idx;
            s_al [h][lane] = e / sum;
        }
    }
    __syncthreads();
    if (f >= F) return;

    int   idx[KNBR];
    float al [KNBR];
    const int4*   si4 = reinterpret_cast<const int4*>(s_idx[sub]);
    const float4* sa4 = reinterpret_cast<const float4*>(s_al[sub]);
#pragma unroll
    for (int q = 0; q < 8; q++) {
        int4   iv = si4[q];
        float4 av = sa4[q];
        idx[q*4+0] = iv.x; idx[q*4+1] = iv.y; idx[q*4+2] = iv.z; idx[q*4+3] = iv.w;
        al [q*4+0] = av.x; al [q*4+1] = av.y; al [q*4+2] = av.z; al [q*4+3] = av.w;
    }

    const __half2* eh = reinterpret_cast<const __half2*>(g_emb_h);
    float2 acc = make_float2(0.0f, 0.0f);
#pragma unroll
    for (int k = 0; k < KNBR; k++) {
        __half2 hv = __ldg(eh + (size_t)((unsigned)idx[k]) * (EMB / 2) + ep);
        float2  v  = __half22float2(hv);
        acc.x = fmaf(al[k], v.x, acc.x);
        acc.y = fmaf(al[k], v.y, acc.y);
    }
    *reinterpret_cast<float2*>(&g_agg[(size_t)f * EMB + 2 * ep]) = acc;
}

// ---------------------------------------------------------------------------
// Kernel C: tensor-core gate+fuse.
// gate = sigmoid(cat([emb_f, agg]) @ W.T + b); out = gate*emb_f + (1-gate)*agg
// fp16 mma.sync m16n8k16, fp32 accumulate. 256 threads = 8 warps (4f x 2e);
// warp tile 16f x 64e; K = 256 in 16 steps. W fp16 resident in smem (loaded
// once per block); cat tile fp32->fp16 per 64-f tile. Persistent grid.
// ---------------------------------------------------------------------------
#define TM 64
#define W_LDH   136   // halves per k-row (128 + 8 pad): 272B stride
#define CAT_LDH 264   // halves per f-row (256 + 8 pad): 528B stride
#define S_W_HALFS   (256 * W_LDH)    // 69632 B
#define S_CAT_HALFS (TM * CAT_LDH)   // 33792 B
#define SMEM_GATE_B ((S_W_HALFS + S_CAT_HALFS) * 2)

__global__ __launch_bounds__(256, 2) void gate_fuse_kernel(
    const float* __restrict__ emb_f,  // [F, 128]
    const float* __restrict__ W,      // [128, 256] row-major (e, j)
    const float* __restrict__ bias,   // [128]
    float* __restrict__ out,          // [F, 128]
    int F)
{
    extern __shared__ __half hsmem[];
    __half* s_w   = hsmem;                 // [k=0..255][n=0..127] (+pad)
    __half* s_cat = hsmem + S_W_HALFS;     // [f=0..63][k=0..255] (+pad)

    const int t    = threadIdx.x;
    const int lane = t & 31;
    const int wid  = t >> 5;
    const int wf   = wid >> 1;        // 0..3  -> f0 = 16*wf
    const int we   = wid & 1;         // 0..1  -> n_base = 64*we
    const int f0   = wf * 16;
    const int nb   = we * 64;
    const int ntiles = (F + TM - 1) / TM;

    // ---- Convert W to fp16 smem [k][n] (transpose), once per block ----
#pragma unroll 8
    for (int r = 0; r < 128; r++) {
        int id = t + 256 * r;             // over 32768 = 128*256
        int e  = id >> 8;                 // 0..127
        int j  = id & 255;                // 0..255
        s_w[j * W_LDH + e] = __float2half_rn(W[e * 256 + j]);
    }
    __syncthreads();

    const uint32_t s_cat_u = (uint32_t)__cvta_generic_to_shared(s_cat);
    const uint32_t s_w_u   = (uint32_t)__cvta_generic_to_shared(s_w);

    // ldmatrix base addresses (per-lane, tile-invariant parts)
    // A: row = f0 + (lane&15), colofs = (lane>>4)*8
    const uint32_t a_lane_addr = s_cat_u +
        (uint32_t)(((f0 + (lane & 15)) * CAT_LDH + (lane >> 4) * 8) * 2);
    // B: row = ((lane>>3)&1)*8 + (lane&7), col = nb + (lane>>4)*8
    const uint32_t b_lane_addr = s_w_u +
        (uint32_t)(((((lane >> 3) & 1) * 8 + (lane & 7)) * W_LDH
                    + nb + (lane >> 4) * 8) * 2);

#pragma unroll 1
    for (int tile = blockIdx.x; tile < ntiles; tile += gridDim.x) {
        const int fbase = tile * TM;

        // ---- Load cat tile: fp32 -> fp16 smem. row = t>>2, col4 = (t&3)+4i
        {
            const int row = t >> 2;
            int gf = fbase + row; if (gf >= F) gf = F - 1;
            const float* ef = emb_f + (size_t)gf * EMB;
            const float* ag = g_agg + (size_t)gf * EMB;
            __half* dst = s_cat + row * CAT_LDH;
#pragma unroll
            for (int i = 0; i < 16; i++) {
                int col4 = (t & 3) + 4 * i;         // 0..63
                int col  = col4 * 4;
                float4 v = (col < 128)
                    ? *reinterpret_cast<const float4*>(ef + col)
                    : *reinterpret_cast<const float4*>(ag + col - 128);
                __half2 h0 = __float22half2_rn(make_float2(v.x, v.y));
                __half2 h1 = __float22half2_rn(make_float2(v.z, v.w));
                uint2 hw;
                hw.x = *reinterpret_cast<uint32_t*>(&h0);
                hw.y = *reinterpret_cast<uint32_t*>(&h1);
                *reinterpret_cast<uint2*>(dst + col) = hw;
            }
        }
        __syncthreads();

        // ---- MMA mainloop over K=256 ----
        float acc[32];
#pragma unroll
        for (int i = 0; i < 32; i++) acc[i] = 0.0f;

#pragma unroll
        for (int ks = 0; ks < 16; ks++) {
            const int k0 = ks * 16;
            uint32_t a[4];
            ldsm_x4(a[0], a[1], a[2], a[3], a_lane_addr + (uint32_t)(k0 * 2));
#pragma unroll
            for (int np = 0; np < 4; np++) {     // n-pair: covers 16 e
                uint32_t b0, b1, b2, b3;
                ldsm_x4_t(b0, b1, b2, b3,
                          b_lane_addr + (uint32_t)((k0 * W_LDH + np * 16) * 2));
                mma16816(&acc[(np * 2 + 0) * 4], a, b0, b1);
                mma16816(&acc[(np * 2 + 1) * 4], a, b2, b3);
            }
        }
        __syncthreads();   // s_cat free for next tile

        // ---- Epilogue: gate + blend ----
        const int r = lane >> 2;             // 0..7
        const int cq = (lane & 3) * 2;       // 0,2,4,6
#pragma unroll
        for (int ti = 0; ti < 8; ti++) {
            int c = nb + ti * 8 + cq;
            float2 b2v = *reinterpret_cast<const float2*>(bias + c);
#pragma unroll
            for (int h = 0; h < 2; h++) {
                int f = fbase + f0 + r + 8 * h;
                if (f >= F) continue;
                float x0 = acc[ti * 4 + 2 * h]     + b2v.x;
                float x1 = acc[ti * 4 + 2 * h + 1] + b2v.y;
                float g0 = 1.0f / (1.0f + __expf(-x0));
                float g1 = 1.0f / (1.0f + __expf(-x1));
                float2 ef = *reinterpret_cast<const float2*>(emb_f + (size_t)f * EMB + c);
                float2 ag = *reinterpret_cast<const float2*>(g_agg + (size_t)f * EMB + c);
                float2 o;
                o.x = g0 * ef.x + (1.0f - g0) * ag.x;
                o.y = g1 * ef.y + (1.0f - g1) * ag.y;
                *reinterpret_cast<float2*>(out + (size_t)f * EMB + c) = o;
            }
        }
    }
}

// ---------------------------------------------------------------------------
extern "C" void kernel_launch(void* const* d_in, const int* in_sizes, int n_in,
                              void* d_out, int out_size)
{
    const int*   adj   = (const int*)d_in[0];     // [F,32]
    const float* emb_i = (const float*)d_in[1];   // [N,128]
    const float* emb_f = (const float*)d_in[2];   // [F,128]
    const float* u     = (const float*)d_in[3];   // [128]
    const float* W     = (const float*)d_in[4];   // [128,256]
    const float* bias  = (const float*)d_in[5];   // [128]
    float*       out   = (float*)d_out;           // [F,128]

    const int F = in_sizes[0] / KNBR;
    const int N = in_sizes[1] / EMB;

    int nsm = 148;
    cudaDeviceGetAttribute(&nsm, cudaDevAttrMultiProcessorCount, 0);

    cudaFuncSetAttribute(gate_fuse_kernel,
                         cudaFuncAttributeMaxDynamicSharedMemorySize, SMEM_GATE_B);

    p_kernel<<<(N * 32 + 255) / 256, 256>>>(emb_i, u, N);
    agg_kernel<<<(F + 3) / 4, 256>>>(adj, F);

    int ntiles = (F + TM - 1) / TM;
    int nblk = 2 * nsm;
    if (nblk > ntiles) nblk = ntiles;
    gate_fuse_kernel<<<nblk, 256, SMEM_GATE_B>>>(emb_f, W, bias, out, F);
}